// round 15
// baseline (speedup 1.0000x reference)
#include <cuda_runtime.h>
#include <cuda_bf16.h>
#include <cstdint>

#define HH 112
#define WW 112
#define CIN 64
#define COUTC 128
#define NB 32
#define NTILES 1568          // 32 images * 7 * 7 tiles of 16x16 px
#define GRID_CONV 152

// Scratch: quantized weights [tap][cout][cin] bf16, XOR-8 swizzle pre-applied.
__device__ __align__(16) __nv_bfloat16 g_Wb[9 * COUTC * CIN];     // 144 KB

// ---------------------------------------------------------------------------
__device__ __forceinline__ uint32_t smem_u32(const void* p) {
    uint32_t a;
    asm("{ .reg .u64 t; cvta.to.shared.u64 t, %1; cvt.u32.u64 %0, t; }" : "=r"(a) : "l"(p));
    return a;
}
#define CP_ASYNC16(dst, src) \
    asm volatile("cp.async.cg.shared.global [%0], [%1], 16;\n" :: "r"(dst), "l"(src))
#define CP_COMMIT()   asm volatile("cp.async.commit_group;\n" ::: "memory")
#define CP_WAIT(N)    asm volatile("cp.async.wait_group %0;\n" :: "n"(N) : "memory")
#define STS_ZERO16(dst) \
    asm volatile("st.shared.v4.b32 [%0], {%1,%1,%1,%1};" :: "r"(dst), "r"(0) : "memory")
#define STS128(dst, u) \
    asm volatile("st.shared.v4.b32 [%0], {%1,%2,%3,%4};" \
                 :: "r"(dst), "r"((u).x), "r"((u).y), "r"((u).z), "r"((u).w) : "memory")

#define LDSM_X4(r, addr)                                                          \
    asm volatile("ldmatrix.sync.aligned.m8n8.x4.shared.b16 {%0,%1,%2,%3}, [%4];"  \
        : "=r"((r)[0]), "=r"((r)[1]), "=r"((r)[2]), "=r"((r)[3]) : "r"(addr))

#define MMA_BF16(c, A, B0, B1)                                                    \
    asm volatile("mma.sync.aligned.m16n8k16.row.col.f32.bf16.bf16.f32 "           \
        "{%0,%1,%2,%3},{%4,%5,%6,%7},{%8,%9},{%0,%1,%2,%3};"                      \
        : "+f"((c)[0]), "+f"((c)[1]), "+f"((c)[2]), "+f"((c)[3])                  \
        : "r"((A)[0]), "r"((A)[1]), "r"((A)[2]), "r"((A)[3]), "r"(B0), "r"(B1))

__device__ __forceinline__ unsigned q_bf16x2(float a, float b) {
    int qa = min(127, max(-128, __float2int_rn(a * 128.f)));
    int qb = min(127, max(-128, __float2int_rn(b * 128.f)));
    __nv_bfloat162 p = __halves2bfloat162(__float2bfloat16((float)qa),
                                          __float2bfloat16((float)qb));
    return reinterpret_cast<unsigned&>(p);
}

// ---------------------------------------------------------------------------
// Prep (weights only, ~2us): quantize HWIO -> [tap][cout][cin] bf16,
// 128B rows, chunk c of row r stored at c ^ (r & 7).
// ---------------------------------------------------------------------------
__global__ void quant_w_kernel(const float* __restrict__ k) {
    int o = blockIdx.x * blockDim.x + threadIdx.x;     // (tap*64+cin)*128+cout
    if (o >= 9 * CIN * COUTC) return;
    int tap  = o >> 13;
    int rem  = o & 8191;
    int cin  = rem >> 7;
    int cout = rem & 127;
    int q = min(127, max(-128, __float2int_rn(k[o] * 128.f)));
    int chunk = (cin >> 3) ^ (cout & 7);
    g_Wb[tap * 8192 + cout * 64 + chunk * 8 + (cin & 7)] = __float2bfloat16((float)q);
}

// ---------------------------------------------------------------------------
// Conv: persistent CTAs (152, 1/SM), 512 threads, bf16 mma.sync m16n8k16.
// CTA tile: 256 px (16x16) x 128 cout.  W resident 144KB.
// A: ONE 18x18 halo per tile (40.5KB), double-buffered; 1 sync/tile.
// FUSED QUANTIZATION: halo fill reads fp32 x directly (2x LDG.128), rounds/
// clips/packs to integer-valued bf16, STS.128 into the swizzled halo — the
// separate quant_x pass is gone.
// Warp tile M64 x N32 (grid 4x4); per (kx,ks): 6 A h-row frags shared across
// ky+mt, 6 B frags each feeding 8 MMAs.  Swizzle key per-fragment row&7.
// ---------------------------------------------------------------------------
#define SMEM_S     147456
#define SBUF       41472                  // 324 * 128
#define SMEM_BYTES (147456 + 2 * SBUF)    // 230400

__global__ __launch_bounds__(512, 1) void conv_hmma_kernel(float* __restrict__ out,
                                                           const float* __restrict__ x) {
    extern __shared__ __align__(128) char smem[];
    const int tid  = threadIdx.x;
    const int wid  = tid >> 5;
    const int lane = tid & 31;
    const uint32_t sb = smem_u32(smem);
    const uint32_t sW = sb;
    const uint32_t sS[2] = { sb + SMEM_S, sb + SMEM_S + SBUF };

    const int m0 = (wid & 3) * 64;   // warp M offset (pixels)
    const int n0 = (wid >> 2) * 32;  // warp N offset (couts)

    // A lane geometry: pixel p0 = m0+(lane&15) -> (hA, wA); m0 % 16 == 0
    const int p0 = m0 + (lane & 15);
    const int hA = p0 >> 4;
    const int wA = p0 & 15;
    const uint32_t csA = (uint32_t)(lane >> 4);                       // 0/1

    // B lane geometry (row&7 == lane&7)
    const int sw7B = lane & 7;
    const uint32_t offB = (uint32_t)(n0 + ((lane >> 4) & 1) * 8 + (lane & 7)) * 128;
    const uint32_t csB  = (uint32_t)((lane >> 3) & 1);                // 0/1

    // Fill: quantize fp32 x inline into the swizzled halo (6 chunks/thread)
#define FILL_HALO(T_, buf_) do {                                                   \
        const int n_  = (T_) / 49;                                                 \
        const int rm_ = (T_) - n_ * 49;                                            \
        const int hb_ = (rm_ / 7) * 16 - 1;                                        \
        const int wb_ = (rm_ % 7) * 16 - 1;                                        \
        _Pragma("unroll")                                                          \
        for (int jj = 0; jj < 6; jj++) {                                           \
            const int j = tid + jj * 512;                                          \
            if (j < 2592) {                                                        \
                const int row = j >> 3;                                            \
                const int c   = j & 7;                                             \
                const int rh  = row / 18;                                          \
                const int h_  = hb_ + rh;                                          \
                const int w_  = wb_ + (row - rh * 18);                             \
                const uint32_t dst = sS[buf_] + (uint32_t)row * 128 +              \
                                     (uint32_t)((c ^ (row & 7)) * 16);             \
                if (((unsigned)h_ < HH) && ((unsigned)w_ < WW)) {                  \
                    const float4* s4 = (const float4*)(x +                         \
                        ((size_t)(n_ * HH + h_) * WW + w_) * 64 + c * 8);          \
                    float4 v0 = s4[0];                                             \
                    float4 v1 = s4[1];                                             \
                    uint4 u;                                                       \
                    u.x = q_bf16x2(v0.x, v0.y);                                    \
                    u.y = q_bf16x2(v0.z, v0.w);                                    \
                    u.z = q_bf16x2(v1.x, v1.y);                                    \
                    u.w = q_bf16x2(v1.z, v1.w);                                    \
                    STS128(dst, u);                                                \
                } else {                                                           \
                    STS_ZERO16(dst);                                               \
                }                                                                  \
            }                                                                      \
        }                                                                          \
    } while (0)

    // Prologue: resident W (144KB, cp.async) + first halo (fused LDG fill)
    for (int j = tid; j < 9216; j += 512)
        CP_ASYNC16(sW + j * 16, (const char*)g_Wb + j * 16);
    CP_COMMIT();
    const int T0 = blockIdx.x;
    FILL_HALO(T0, 0);
    CP_WAIT(0);

    int buf = 0;
    for (int T = T0; T < NTILES; T += GRID_CONV) {
        const int n  = T / 49;
        const int rm = T - n * 49;
        const int r0 = (rm / 7) * 16;
        const int c0 = (rm % 7) * 16;

        __syncthreads();             // halo(T) visible; all warps done with buf^1

        if (T + GRID_CONV < NTILES) FILL_HALO(T + GRID_CONV, buf ^ 1);

        float acc[4][4][4];          // [mt][nt][reg]
#pragma unroll
        for (int mt = 0; mt < 4; mt++)
#pragma unroll
            for (int nt = 0; nt < 4; nt++)
#pragma unroll
                for (int j = 0; j < 4; j++) acc[mt][nt][j] = 0.f;

        const uint32_t halo = sS[buf];
#pragma unroll 1
        for (int kx = 0; kx < 3; kx++) {
            const int rowBase = hA * 18 + wA + kx;
#pragma unroll
            for (int ks = 0; ks < 4; ks++) {
                // 6 A fragments: h-rows hA..hA+5 (MMA(ky,mt) uses a[ky+mt])
                uint32_t a[6][4];
#pragma unroll
                for (int hr = 0; hr < 6; hr++) {
                    const int row = rowBase + hr * 18;
                    LDSM_X4(a[hr], halo + (uint32_t)row * 128 +
                            (uint32_t)(((2 * ks + csA) ^ (row & 7)) * 16));
                }
                const uint32_t cb = (uint32_t)(((2 * ks + csB) ^ sw7B) * 16);
#pragma unroll
                for (int ky = 0; ky < 3; ky++) {
                    const uint32_t wb = sW + (uint32_t)(ky * 3 + kx) * 16384;
#pragma unroll
                    for (int p = 0; p < 2; p++) {
                        uint32_t b[4];
                        LDSM_X4(b, wb + offB + (uint32_t)p * 2048 + cb);
#pragma unroll
                        for (int mt = 0; mt < 4; mt++) {
                            MMA_BF16(acc[mt][2 * p],     a[ky + mt], b[0], b[1]);
                            MMA_BF16(acc[mt][2 * p + 1], a[ky + mt], b[2], b[3]);
                        }
                    }
                }
            }
        }

        // Epilogue: out = floor(acc * 2^-7) * 2^-7   (exact)
#pragma unroll
        for (int mt = 0; mt < 4; mt++) {
            const int px1 = m0 + mt * 16 + (lane >> 2);
            const int px2 = px1 + 8;
            float* o1 = out + (((size_t)(n * HH + r0 + (px1 >> 4)) * WW +
                                (c0 + (px1 & 15))) << 7);
            float* o2 = out + (((size_t)(n * HH + r0 + (px2 >> 4)) * WW +
                                (c0 + (px2 & 15))) << 7);
            const int col = n0 + (lane & 3) * 2;
#pragma unroll
            for (int nt = 0; nt < 4; nt++) {
                float2 v;
                v.x = floorf(acc[mt][nt][0] * 0.0078125f) * 0.0078125f;
                v.y = floorf(acc[mt][nt][1] * 0.0078125f) * 0.0078125f;
                *(float2*)(o1 + col + nt * 8) = v;
                v.x = floorf(acc[mt][nt][2] * 0.0078125f) * 0.0078125f;
                v.y = floorf(acc[mt][nt][3] * 0.0078125f) * 0.0078125f;
                *(float2*)(o2 + col + nt * 8) = v;
            }
        }
        buf ^= 1;
    }
}

extern "C" void kernel_launch(void* const* d_in, const int* in_sizes, int n_in,
                              void* d_out, int out_size) {
    const float* x = (const float*)d_in[0];   // [32,112,112,64] fp32 NHWC
    const float* k = (const float*)d_in[1];   // [3,3,64,128] fp32 HWIO
    float* out = (float*)d_out;               // [32,112,112,128] fp32

    cudaFuncSetAttribute(conv_hmma_kernel,
                         cudaFuncAttributeMaxDynamicSharedMemorySize, SMEM_BYTES);

    quant_w_kernel<<<(9 * CIN * COUTC + 255) / 256, 256>>>(k);
    conv_hmma_kernel<<<GRID_CONV, 512, SMEM_BYTES>>>(out, x);
}

// round 16
// speedup vs baseline: 1.0351x; 1.0351x over previous
#include <cuda_runtime.h>
#include <cuda_bf16.h>
#include <cstdint>

#define HH 112
#define WW 112
#define CIN 64
#define COUTC 128
#define NB 32
#define NTILES 1568          // 32 images * 7 * 7 tiles of 16x16 px
#define GRID_CONV 152

// Scratch: quantized activations as integer-valued bf16 (exact), NHWC; and
// weights [tap][cout][cin] bf16 with the XOR-8 smem swizzle pre-applied.
__device__ __align__(16) __nv_bfloat16 g_Xb[NB * HH * WW * CIN];  // ~51.4 MB
__device__ __align__(16) __nv_bfloat16 g_Wb[9 * COUTC * CIN];     // 144 KB

// ---------------------------------------------------------------------------
__device__ __forceinline__ uint32_t smem_u32(const void* p) {
    uint32_t a;
    asm("{ .reg .u64 t; cvta.to.shared.u64 t, %1; cvt.u32.u64 %0, t; }" : "=r"(a) : "l"(p));
    return a;
}
#define CP_ASYNC16(dst, src) \
    asm volatile("cp.async.cg.shared.global [%0], [%1], 16;\n" :: "r"(dst), "l"(src))
#define CP_COMMIT()   asm volatile("cp.async.commit_group;\n" ::: "memory")
#define CP_WAIT(N)    asm volatile("cp.async.wait_group %0;\n" :: "n"(N) : "memory")
#define STS_ZERO16(dst) \
    asm volatile("st.shared.v4.b32 [%0], {%1,%1,%1,%1};" :: "r"(dst), "r"(0) : "memory")

#define LDSM_X4(r, addr)                                                          \
    asm volatile("ldmatrix.sync.aligned.m8n8.x4.shared.b16 {%0,%1,%2,%3}, [%4];"  \
        : "=r"((r)[0]), "=r"((r)[1]), "=r"((r)[2]), "=r"((r)[3]) : "r"(addr))

#define MMA_BF16(c, A, B0, B1)                                                    \
    asm volatile("mma.sync.aligned.m16n8k16.row.col.f32.bf16.bf16.f32 "           \
        "{%0,%1,%2,%3},{%4,%5,%6,%7},{%8,%9},{%0,%1,%2,%3};"                      \
        : "+f"((c)[0]), "+f"((c)[1]), "+f"((c)[2]), "+f"((c)[3])                  \
        : "r"((A)[0]), "r"((A)[1]), "r"((A)[2]), "r"((A)[3]), "r"(B0), "r"(B1))

__device__ __forceinline__ unsigned q_bf16x2(float a, float b) {
    int qa = min(127, max(-128, __float2int_rn(a * 128.f)));
    int qb = min(127, max(-128, __float2int_rn(b * 128.f)));
    __nv_bfloat162 p = __halves2bfloat162(__float2bfloat16((float)qa),
                                          __float2bfloat16((float)qb));
    return reinterpret_cast<unsigned&>(p);
}

// ---------------------------------------------------------------------------
// Fused prep (512 threads): blocks [0,18) quantize+relayout W; the rest
// quantize X, 8 floats/thread, __ldcs (evict-first: x is read-once-dead,
// keep L2 for the g_Xb image the conv re-reads).
// ---------------------------------------------------------------------------
#define WBLK 18
__global__ __launch_bounds__(512) void quant_prep_kernel(const float* __restrict__ x,
                                                         const float* __restrict__ k) {
    const int b = blockIdx.x;
    if (b < WBLK) {
        int o = b * 4096 + threadIdx.x;          // 18*4096 = 73728 = 9*64*128
#pragma unroll
        for (int j = 0; j < 8; j++, o += 512) {
            int tap  = o >> 13;
            int rem  = o & 8191;
            int cin  = rem >> 7;
            int cout = rem & 127;
            int q = min(127, max(-128, __float2int_rn(k[o] * 128.f)));
            int chunk = (cin >> 3) ^ (cout & 7);
            g_Wb[tap * 8192 + cout * 64 + chunk * 8 + (cin & 7)] =
                __float2bfloat16((float)q);
        }
        return;
    }
    const size_t i = (size_t)(b - WBLK) * 512 + threadIdx.x;   // 8-float group
    const float4* xv = (const float4*)x;
    float4 v0 = __ldcs(xv + i * 2);
    float4 v1 = __ldcs(xv + i * 2 + 1);
    uint4 u;
    u.x = q_bf16x2(v0.x, v0.y);
    u.y = q_bf16x2(v0.z, v0.w);
    u.z = q_bf16x2(v1.x, v1.y);
    u.w = q_bf16x2(v1.z, v1.w);
    ((uint4*)g_Xb)[i] = u;
}

// ---------------------------------------------------------------------------
// Conv (R14 proven): persistent CTAs (152, 1/SM), 512 threads, bf16
// mma.sync m16n8k16.  CTA tile: 256 px (16x16) x 128 cout.  W resident 144KB.
// A: ONE 18x18 halo per tile (40.5KB), double-buffered; 1 sync/tile,
// cp.async fill issued right after the sync (hidden under a full tile).
// Warp tile M64 x N32 (grid 4x4): per (kx,ks) 6 A h-row frags shared across
// ky+mt and 6 B frags each feeding 8 MMAs (LDSM minimal for this shape).
// Swizzle key per-fragment row&7 (R10 lesson).
// ---------------------------------------------------------------------------
#define SMEM_S     147456
#define SBUF       41472                  // 324 * 128
#define SMEM_BYTES (147456 + 2 * SBUF)    // 230400

__global__ __launch_bounds__(512, 1) void conv_hmma_kernel(float* __restrict__ out) {
    extern __shared__ __align__(128) char smem[];
    const int tid  = threadIdx.x;
    const int wid  = tid >> 5;
    const int lane = tid & 31;
    const uint32_t sb = smem_u32(smem);
    const uint32_t sW = sb;
    const uint32_t sS[2] = { sb + SMEM_S, sb + SMEM_S + SBUF };

    const int m0 = (wid & 3) * 64;   // warp M offset (pixels)
    const int n0 = (wid >> 2) * 32;  // warp N offset (couts)

    // A lane geometry: pixel p0 = m0+(lane&15) -> (hA, wA); m0 % 16 == 0
    const int p0 = m0 + (lane & 15);
    const int hA = p0 >> 4;
    const int wA = p0 & 15;
    const uint32_t csA = (uint32_t)(lane >> 4);                       // 0/1

    // B lane geometry (row&7 == lane&7)
    const int sw7B = lane & 7;
    const uint32_t offB = (uint32_t)(n0 + ((lane >> 4) & 1) * 8 + (lane & 7)) * 128;
    const uint32_t csB  = (uint32_t)((lane >> 3) & 1);                // 0/1

#define FILL_HALO(T_, buf_) do {                                                   \
        const int n_  = (T_) / 49;                                                 \
        const int rm_ = (T_) - n_ * 49;                                            \
        const int hb_ = (rm_ / 7) * 16 - 1;                                        \
        const int wb_ = (rm_ % 7) * 16 - 1;                                        \
        _Pragma("unroll")                                                          \
        for (int jj = 0; jj < 6; jj++) {                                           \
            const int j = tid + jj * 512;                                          \
            if (j < 2592) {                                                        \
                const int row = j >> 3;                                            \
                const int c   = j & 7;                                             \
                const int rh  = row / 18;                                          \
                const int h_  = hb_ + rh;                                          \
                const int w_  = wb_ + (row - rh * 18);                             \
                const uint32_t dst = sS[buf_] + (uint32_t)row * 128 +              \
                                     (uint32_t)((c ^ (row & 7)) * 16);             \
                if (((unsigned)h_ < HH) && ((unsigned)w_ < WW)) {                  \
                    const char* src = (const char*)g_Xb +                          \
                        ((size_t)(n_ * HH + h_) * WW + w_) * 128 + c * 16;         \
                    CP_ASYNC16(dst, src);                                          \
                } else {                                                           \
                    STS_ZERO16(dst);                                               \
                }                                                                  \
            }                                                                      \
        }                                                                          \
    } while (0)

    // Prologue: resident W (144KB) + first halo
    for (int j = tid; j < 9216; j += 512)
        CP_ASYNC16(sW + j * 16, (const char*)g_Wb + j * 16);
    const int T0 = blockIdx.x;
    FILL_HALO(T0, 0);
    CP_COMMIT();

    int buf = 0;
    for (int T = T0; T < NTILES; T += GRID_CONV) {
        const int n  = T / 49;
        const int rm = T - n * 49;
        const int r0 = (rm / 7) * 16;
        const int c0 = (rm % 7) * 16;

        CP_WAIT(0);                  // halo(T) complete
        __syncthreads();             // all warps done reading buf^1 (tile T-1)

        if (T + GRID_CONV < NTILES) FILL_HALO(T + GRID_CONV, buf ^ 1);
        CP_COMMIT();

        float acc[4][4][4];          // [mt][nt][reg]
#pragma unroll
        for (int mt = 0; mt < 4; mt++)
#pragma unroll
            for (int nt = 0; nt < 4; nt++)
#pragma unroll
                for (int j = 0; j < 4; j++) acc[mt][nt][j] = 0.f;

        const uint32_t halo = sS[buf];
#pragma unroll 1
        for (int kx = 0; kx < 3; kx++) {
            const int rowBase = hA * 18 + wA + kx;
#pragma unroll
            for (int ks = 0; ks < 4; ks++) {
                // 6 A fragments: h-rows hA..hA+5 (MMA(ky,mt) uses a[ky+mt])
                uint32_t a[6][4];
#pragma unroll
                for (int hr = 0; hr < 6; hr++) {
                    const int row = rowBase + hr * 18;
                    LDSM_X4(a[hr], halo + (uint32_t)row * 128 +
                            (uint32_t)(((2 * ks + csA) ^ (row & 7)) * 16));
                }
                const uint32_t cb = (uint32_t)(((2 * ks + csB) ^ sw7B) * 16);
#pragma unroll
                for (int ky = 0; ky < 3; ky++) {
                    const uint32_t wb = sW + (uint32_t)(ky * 3 + kx) * 16384;
#pragma unroll
                    for (int p = 0; p < 2; p++) {
                        uint32_t b[4];
                        LDSM_X4(b, wb + offB + (uint32_t)p * 2048 + cb);
#pragma unroll
                        for (int mt = 0; mt < 4; mt++) {
                            MMA_BF16(acc[mt][2 * p],     a[ky + mt], b[0], b[1]);
                            MMA_BF16(acc[mt][2 * p + 1], a[ky + mt], b[2], b[3]);
                        }
                    }
                }
            }
        }

        // Epilogue: out = floor(acc * 2^-7) * 2^-7   (exact)
#pragma unroll
        for (int mt = 0; mt < 4; mt++) {
            const int px1 = m0 + mt * 16 + (lane >> 2);
            const int px2 = px1 + 8;
            float* o1 = out + (((size_t)(n * HH + r0 + (px1 >> 4)) * WW +
                                (c0 + (px1 & 15))) << 7);
            float* o2 = out + (((size_t)(n * HH + r0 + (px2 >> 4)) * WW +
                                (c0 + (px2 & 15))) << 7);
            const int col = n0 + (lane & 3) * 2;
#pragma unroll
            for (int nt = 0; nt < 4; nt++) {
                float2 v;
                v.x = floorf(acc[mt][nt][0] * 0.0078125f) * 0.0078125f;
                v.y = floorf(acc[mt][nt][1] * 0.0078125f) * 0.0078125f;
                *(float2*)(o1 + col + nt * 8) = v;
                v.x = floorf(acc[mt][nt][2] * 0.0078125f) * 0.0078125f;
                v.y = floorf(acc[mt][nt][3] * 0.0078125f) * 0.0078125f;
                *(float2*)(o2 + col + nt * 8) = v;
            }
        }
        buf ^= 1;
    }
}

extern "C" void kernel_launch(void* const* d_in, const int* in_sizes, int n_in,
                              void* d_out, int out_size) {
    const float* x = (const float*)d_in[0];   // [32,112,112,64] fp32 NHWC
    const float* k = (const float*)d_in[1];   // [3,3,64,128] fp32 HWIO
    float* out = (float*)d_out;               // [32,112,112,128] fp32

    cudaFuncSetAttribute(conv_hmma_kernel,
                         cudaFuncAttributeMaxDynamicSharedMemorySize, SMEM_BYTES);

    int nx8b = NB * HH * WW * CIN / 8 / 512;  // 6272 x-blocks of 512 thr
    quant_prep_kernel<<<WBLK + nx8b, 512>>>(x, k);
    conv_hmma_kernel<<<GRID_CONV, 512, SMEM_BYTES>>>(out);
}

// round 17
// speedup vs baseline: 1.0509x; 1.0152x over previous
#include <cuda_runtime.h>
#include <cuda_bf16.h>
#include <cstdint>

#define HH 112
#define WW 112
#define CIN 64
#define COUTC 128
#define NB 32
#define NTILES_MAIN 1520     // 152 CTAs x 10 full 16x16 tiles
#define NTAIL 96             // 48 remaining tiles split into 96 half-tiles (8x16)
#define GRID_CONV 152

// Scratch: quantized activations as integer-valued bf16 (exact), NHWC; and
// weights [tap][cout][cin] bf16 with the XOR-8 smem swizzle pre-applied.
__device__ __align__(16) __nv_bfloat16 g_Xb[NB * HH * WW * CIN];  // ~51.4 MB
__device__ __align__(16) __nv_bfloat16 g_Wb[9 * COUTC * CIN];     // 144 KB

// ---------------------------------------------------------------------------
__device__ __forceinline__ uint32_t smem_u32(const void* p) {
    uint32_t a;
    asm("{ .reg .u64 t; cvta.to.shared.u64 t, %1; cvt.u32.u64 %0, t; }" : "=r"(a) : "l"(p));
    return a;
}
#define CP_ASYNC16(dst, src) \
    asm volatile("cp.async.cg.shared.global [%0], [%1], 16;\n" :: "r"(dst), "l"(src))
#define CP_COMMIT()   asm volatile("cp.async.commit_group;\n" ::: "memory")
#define CP_WAIT(N)    asm volatile("cp.async.wait_group %0;\n" :: "n"(N) : "memory")
#define STS_ZERO16(dst) \
    asm volatile("st.shared.v4.b32 [%0], {%1,%1,%1,%1};" :: "r"(dst), "r"(0) : "memory")

#define LDSM_X4(r, addr)                                                          \
    asm volatile("ldmatrix.sync.aligned.m8n8.x4.shared.b16 {%0,%1,%2,%3}, [%4];"  \
        : "=r"((r)[0]), "=r"((r)[1]), "=r"((r)[2]), "=r"((r)[3]) : "r"(addr))

#define MMA_BF16(c, A, B0, B1)                                                    \
    asm volatile("mma.sync.aligned.m16n8k16.row.col.f32.bf16.bf16.f32 "           \
        "{%0,%1,%2,%3},{%4,%5,%6,%7},{%8,%9},{%0,%1,%2,%3};"                      \
        : "+f"((c)[0]), "+f"((c)[1]), "+f"((c)[2]), "+f"((c)[3])                  \
        : "r"((A)[0]), "r"((A)[1]), "r"((A)[2]), "r"((A)[3]), "r"(B0), "r"(B1))

__device__ __forceinline__ unsigned q_bf16x2(float a, float b) {
    int qa = min(127, max(-128, __float2int_rn(a * 128.f)));
    int qb = min(127, max(-128, __float2int_rn(b * 128.f)));
    __nv_bfloat162 p = __halves2bfloat162(__float2bfloat16((float)qa),
                                          __float2bfloat16((float)qb));
    return reinterpret_cast<unsigned&>(p);
}

// ---------------------------------------------------------------------------
// Fused prep (512 threads): blocks [0,18) quantize+relayout W; the rest
// quantize X, 8 floats/thread, __ldcs on the read-once x.
// ---------------------------------------------------------------------------
#define WBLK 18
__global__ __launch_bounds__(512) void quant_prep_kernel(const float* __restrict__ x,
                                                         const float* __restrict__ k) {
    const int b = blockIdx.x;
    if (b < WBLK) {
        int o = b * 4096 + threadIdx.x;          // 18*4096 = 73728 = 9*64*128
#pragma unroll
        for (int j = 0; j < 8; j++, o += 512) {
            int tap  = o >> 13;
            int rem  = o & 8191;
            int cin  = rem >> 7;
            int cout = rem & 127;
            int q = min(127, max(-128, __float2int_rn(k[o] * 128.f)));
            int chunk = (cin >> 3) ^ (cout & 7);
            g_Wb[tap * 8192 + cout * 64 + chunk * 8 + (cin & 7)] =
                __float2bfloat16((float)q);
        }
        return;
    }
    const size_t i = (size_t)(b - WBLK) * 512 + threadIdx.x;   // 8-float group
    const float4* xv = (const float4*)x;
    float4 v0 = __ldcs(xv + i * 2);
    float4 v1 = __ldcs(xv + i * 2 + 1);
    uint4 u;
    u.x = q_bf16x2(v0.x, v0.y);
    u.y = q_bf16x2(v0.z, v0.w);
    u.z = q_bf16x2(v1.x, v1.y);
    u.w = q_bf16x2(v1.z, v1.w);
    ((uint4*)g_Xb)[i] = u;
}

// ---------------------------------------------------------------------------
// Conv: persistent CTAs (152, 1/SM), 512 threads, bf16 mma.sync m16n8k16.
// Main: 10 full tiles/CTA (16x16 px x 128 cout), 18x18 halo, 1 sync/tile.
// Tail: 48 leftover tiles split into 96 HALF-tiles (8x16 px) on CTAs 0..95
// (critical path 11 -> 10.5 tile-equivalents).  Tail halo 10x18 rows.
// Warp tile M64xN32 (main) / M32xN32 (tail); swizzle key per-fragment row&7.
// ---------------------------------------------------------------------------
#define SMEM_S     147456
#define SBUF       41472                  // 324 * 128
#define SMEM_BYTES (147456 + 2 * SBUF)    // 230400

__global__ __launch_bounds__(512, 1) void conv_hmma_kernel(float* __restrict__ out) {
    extern __shared__ __align__(128) char smem[];
    const int tid  = threadIdx.x;
    const int wid  = tid >> 5;
    const int lane = tid & 31;
    const uint32_t sb = smem_u32(smem);
    const uint32_t sW = sb;
    const uint32_t sS[2] = { sb + SMEM_S, sb + SMEM_S + SBUF };
    const int cta = blockIdx.x;

    const int m0 = (wid & 3) * 64;   // warp M offset (pixels, main)
    const int n0 = (wid >> 2) * 32;  // warp N offset (couts)

    // A lane geometry (main): pixel p0 = m0+(lane&15) -> (hA, wA)
    const int p0 = m0 + (lane & 15);
    const int hA = p0 >> 4;
    const int wA = p0 & 15;
    const uint32_t csA = (uint32_t)(lane >> 4);                       // 0/1

    // B lane geometry (row&7 == lane&7)
    const int sw7B = lane & 7;
    const uint32_t offB = (uint32_t)(n0 + ((lane >> 4) & 1) * 8 + (lane & 7)) * 128;
    const uint32_t csB  = (uint32_t)((lane >> 3) & 1);                // 0/1

    // generic halo fill: NR rows of (h0+rh, w0+rw) 18-wide strip
#define FILL_ROWS(NROWS, NITER, n_, h0_, w0_, buf_) do {                           \
        _Pragma("unroll")                                                          \
        for (int jj = 0; jj < (NITER); jj++) {                                     \
            const int j = tid + jj * 512;                                          \
            if (j < (NROWS) * 8) {                                                 \
                const int row = j >> 3;                                            \
                const int c   = j & 7;                                             \
                const int rh  = row / 18;                                          \
                const int h_  = (h0_) + rh;                                        \
                const int w_  = (w0_) + (row - rh * 18);                           \
                const uint32_t dst = sS[buf_] + (uint32_t)row * 128 +              \
                                     (uint32_t)((c ^ (row & 7)) * 16);             \
                if (((unsigned)h_ < HH) && ((unsigned)w_ < WW)) {                  \
                    const char* src = (const char*)g_Xb +                          \
                        ((size_t)((n_) * HH + h_) * WW + w_) * 128 + c * 16;       \
                    CP_ASYNC16(dst, src);                                          \
                } else {                                                           \
                    STS_ZERO16(dst);                                               \
                }                                                                  \
            }                                                                      \
        }                                                                          \
    } while (0)

#define FILL_HALO(T_, buf_) do {                                                   \
        const int nn_  = (T_) / 49;                                               \
        const int rmm_ = (T_) - nn_ * 49;                                          \
        FILL_ROWS(324, 6, nn_, (rmm_ / 7) * 16 - 1, (rmm_ % 7) * 16 - 1, buf_);    \
    } while (0)

    // Tail assignment: CTA b<96 -> unit u=b: tile 1520+(u>>1), half u&1
    const int tT  = NTILES_MAIN + (cta >> 1);
    const int thh = cta & 1;
#define FILL_TAIL(buf_) do {                                                       \
        const int nn_  = tT / 49;                                                  \
        const int rmm_ = tT - nn_ * 49;                                            \
        FILL_ROWS(180, 3, nn_, (rmm_ / 7) * 16 + thh * 8 - 1,                      \
                  (rmm_ % 7) * 16 - 1, buf_);                                      \
    } while (0)

    // Prologue: resident W (144KB) + first halo
    for (int j = tid; j < 9216; j += 512)
        CP_ASYNC16(sW + j * 16, (const char*)g_Wb + j * 16);
    FILL_HALO(cta, 0);
    CP_COMMIT();

    int buf = 0;
    for (int T = cta; T < NTILES_MAIN; T += GRID_CONV) {
        const int n  = T / 49;
        const int rm = T - n * 49;
        const int r0 = (rm / 7) * 16;
        const int c0 = (rm % 7) * 16;

        CP_WAIT(0);                  // halo(T) complete
        __syncthreads();             // all warps done reading buf^1

        if (T + GRID_CONV < NTILES_MAIN) FILL_HALO(T + GRID_CONV, buf ^ 1);
        else if (cta < NTAIL)            FILL_TAIL(buf ^ 1);
        CP_COMMIT();

        float acc[4][4][4];          // [mt][nt][reg]
#pragma unroll
        for (int mt = 0; mt < 4; mt++)
#pragma unroll
            for (int nt = 0; nt < 4; nt++)
#pragma unroll
                for (int j = 0; j < 4; j++) acc[mt][nt][j] = 0.f;

        const uint32_t halo = sS[buf];
#pragma unroll 1
        for (int kx = 0; kx < 3; kx++) {
            const int rowBase = hA * 18 + wA + kx;
#pragma unroll
            for (int ks = 0; ks < 4; ks++) {
                uint32_t a[6][4];
#pragma unroll
                for (int hr = 0; hr < 6; hr++) {
                    const int row = rowBase + hr * 18;
                    LDSM_X4(a[hr], halo + (uint32_t)row * 128 +
                            (uint32_t)(((2 * ks + csA) ^ (row & 7)) * 16));
                }
                const uint32_t cb = (uint32_t)(((2 * ks + csB) ^ sw7B) * 16);
#pragma unroll
                for (int ky = 0; ky < 3; ky++) {
                    const uint32_t wb = sW + (uint32_t)(ky * 3 + kx) * 16384;
#pragma unroll
                    for (int p = 0; p < 2; p++) {
                        uint32_t b[4];
                        LDSM_X4(b, wb + offB + (uint32_t)p * 2048 + cb);
#pragma unroll
                        for (int mt = 0; mt < 4; mt++) {
                            MMA_BF16(acc[mt][2 * p],     a[ky + mt], b[0], b[1]);
                            MMA_BF16(acc[mt][2 * p + 1], a[ky + mt], b[2], b[3]);
                        }
                    }
                }
            }
        }

        // Epilogue: out = floor(acc * 2^-7) * 2^-7   (exact)
#pragma unroll
        for (int mt = 0; mt < 4; mt++) {
            const int px1 = m0 + mt * 16 + (lane >> 2);
            const int px2 = px1 + 8;
            float* o1 = out + (((size_t)(n * HH + r0 + (px1 >> 4)) * WW +
                                (c0 + (px1 & 15))) << 7);
            float* o2 = out + (((size_t)(n * HH + r0 + (px2 >> 4)) * WW +
                                (c0 + (px2 & 15))) << 7);
            const int col = n0 + (lane & 3) * 2;
#pragma unroll
            for (int nt = 0; nt < 4; nt++) {
                float2 v;
                v.x = floorf(acc[mt][nt][0] * 0.0078125f) * 0.0078125f;
                v.y = floorf(acc[mt][nt][1] * 0.0078125f) * 0.0078125f;
                *(float2*)(o1 + col + nt * 8) = v;
                v.x = floorf(acc[mt][nt][2] * 0.0078125f) * 0.0078125f;
                v.y = floorf(acc[mt][nt][3] * 0.0078125f) * 0.0078125f;
                *(float2*)(o2 + col + nt * 8) = v;
            }
        }
        buf ^= 1;
    }

    // ---- Tail: half tile (8x16 px) for CTAs 0..95 ----
    if (cta < NTAIL) {
        const int n  = tT / 49;
        const int rm = tT - n * 49;
        const int r0 = (rm / 7) * 16 + thh * 8;
        const int c0 = (rm % 7) * 16;

        CP_WAIT(0);
        __syncthreads();

        // M32 warp tile: warp grid 4x4 over 128 px
        const int m0t = (wid & 3) * 32;
        const int p0t = m0t + (lane & 15);
        const int hAt = p0t >> 4;          // 0..7
        const int wAt = p0t & 15;

        float acc[2][4][4];
#pragma unroll
        for (int mt = 0; mt < 2; mt++)
#pragma unroll
            for (int nt = 0; nt < 4; nt++)
#pragma unroll
                for (int j = 0; j < 4; j++) acc[mt][nt][j] = 0.f;

        const uint32_t halo = sS[buf];
#pragma unroll 1
        for (int kx = 0; kx < 3; kx++) {
            const int rowBase = hAt * 18 + wAt + kx;
#pragma unroll
            for (int ks = 0; ks < 4; ks++) {
                uint32_t a[4][4];
#pragma unroll
                for (int hr = 0; hr < 4; hr++) {
                    const int row = rowBase + hr * 18;
                    LDSM_X4(a[hr], halo + (uint32_t)row * 128 +
                            (uint32_t)(((2 * ks + csA) ^ (row & 7)) * 16));
                }
                const uint32_t cb = (uint32_t)(((2 * ks + csB) ^ sw7B) * 16);
#pragma unroll
                for (int ky = 0; ky < 3; ky++) {
                    const uint32_t wb = sW + (uint32_t)(ky * 3 + kx) * 16384;
#pragma unroll
                    for (int p = 0; p < 2; p++) {
                        uint32_t b[4];
                        LDSM_X4(b, wb + offB + (uint32_t)p * 2048 + cb);
#pragma unroll
                        for (int mt = 0; mt < 2; mt++) {
                            MMA_BF16(acc[mt][2 * p],     a[ky + mt], b[0], b[1]);
                            MMA_BF16(acc[mt][2 * p + 1], a[ky + mt], b[2], b[3]);
                        }
                    }
                }
            }
        }

#pragma unroll
        for (int mt = 0; mt < 2; mt++) {
            const int px1 = m0t + mt * 16 + (lane >> 2);
            const int px2 = px1 + 8;
            float* o1 = out + (((size_t)(n * HH + r0 + (px1 >> 4)) * WW +
                                (c0 + (px1 & 15))) << 7);
            float* o2 = out + (((size_t)(n * HH + r0 + (px2 >> 4)) * WW +
                                (c0 + (px2 & 15))) << 7);
            const int col = n0 + (lane & 3) * 2;
#pragma unroll
            for (int nt = 0; nt < 4; nt++) {
                float2 v;
                v.x = floorf(acc[mt][nt][0] * 0.0078125f) * 0.0078125f;
                v.y = floorf(acc[mt][nt][1] * 0.0078125f) * 0.0078125f;
                *(float2*)(o1 + col + nt * 8) = v;
                v.x = floorf(acc[mt][nt][2] * 0.0078125f) * 0.0078125f;
                v.y = floorf(acc[mt][nt][3] * 0.0078125f) * 0.0078125f;
                *(float2*)(o2 + col + nt * 8) = v;
            }
        }
    }
}

extern "C" void kernel_launch(void* const* d_in, const int* in_sizes, int n_in,
                              void* d_out, int out_size) {
    const float* x = (const float*)d_in[0];   // [32,112,112,64] fp32 NHWC
    const float* k = (const float*)d_in[1];   // [3,3,64,128] fp32 HWIO
    float* out = (float*)d_out;               // [32,112,112,128] fp32

    cudaFuncSetAttribute(conv_hmma_kernel,
                         cudaFuncAttributeMaxDynamicSharedMemorySize, SMEM_BYTES);

    int nx8b = NB * HH * WW * CIN / 8 / 512;  // 6272 x-blocks of 512 thr
    quant_prep_kernel<<<WBLK + nx8b, 512>>>(x, k);
    conv_hmma_kernel<<<GRID_CONV, 512, SMEM_BYTES>>>(out);
}